// round 6
// baseline (speedup 1.0000x reference)
#include <cuda_runtime.h>

#define EPS 1e-6f
typedef unsigned long long u64t;

#define MUL2(d,a,b)    asm("mul.rn.f32x2 %0, %1, %2;" : "=l"(d) : "l"(a), "l"(b))
#define FMA2(d,a,b,c)  asm("fma.rn.f32x2 %0, %1, %2, %3;" : "=l"(d) : "l"(a), "l"(b), "l"(c))
#define PACK2(d,lo,hi) asm("mov.b64 %0, {%1, %2};" : "=l"(d) : "f"(lo), "f"(hi))
#define UNPACK2(lo,hi,s) asm("mov.b64 {%0, %1}, %2;" : "=f"(lo), "=f"(hi) : "l"(s))

// Scratch (device globals: no allocation allowed)
__device__ float g_xr[256*128*64];     // xr in BINARY blade order, 8 MB
__device__ float g_coef[128*64*64];    // coef[n][k_bin][j_bin], 2 MB
__device__ float g_sgnb[64*64];        // cayley sign per (k_bin,j_bin)
__device__ float g_xp[256*8960];       // x pre-packed pair layout, 9.2 MB
__device__ float g_wp[4*16512];        // w pre-packed pair layout, 264 KB
__device__ int   g_b2s[64];            // binary blade -> sorted index
__device__ int   g_s2c[64];            // sorted index -> class-order pos
__device__ int   g_c2s[64];            // class-order pos -> sorted index
__device__ int   g_c2b[64];            // class-order pos -> binary blade
__device__ int   g_qcls[16];           // class per class-order quad

// ---------------------------------------------------------------------------
// Setup A: orderings + sign table in binary order (i = j ^ k). grid 16 x 256.
__global__ void k_setup_tables(const float* __restrict__ cayley) {
    __shared__ int s_of_b[64];
    int t = threadIdx.x;
    if (t < 64) {
        int pc = __popc(t);
        int rank = 0;
        for (int u = 0; u < 64; u++) {
            int pu = __popc(u);
            rank += (pu < pc) || (pu == pc && u < t);
        }
        s_of_b[t] = rank;
    }
    __syncthreads();
    if (blockIdx.x == 0 && t < 64) {
        g_b2s[t] = s_of_b[t];
        int c = __popc(t) & 3;
        int s = s_of_b[t];
        int co = 0;
        for (int u = 0; u < 64; u++) {
            int cu = __popc(u) & 3;
            co += (cu < c) || (cu == c && s_of_b[u] < s);
        }
        g_s2c[s] = co;
        g_c2s[co] = s;
        g_c2b[co] = t;
        if ((co & 3) == 0) g_qcls[co >> 2] = c;
    }
    int idx = blockIdx.x*256 + t;            // idx = k*64 + j (binary)
    int k = idx >> 6, j = idx & 63, i = j ^ k;
    g_sgnb[idx] = cayley[s_of_b[i]*4096 + s_of_b[j]*64 + s_of_b[k]];
}

// Setup B: per n, coef[k_bin][j_bin] = sgn * f4[cls(i)][cls(j)][cls(k)].
__global__ void k_setup_coef(const float* __restrict__ w_gp,
                             const int* __restrict__ pidx, int P) {
    __shared__ float f4[64];
    int n = blockIdx.x, t = threadIdx.x;
    if (t < 64) f4[t] = 0.f;
    __syncthreads();
    for (int p = t; p < P; p += 256) {
        int code = pidx[3*p]*16 + pidx[3*p+1]*4 + pidx[3*p+2];
        f4[code] = w_gp[n*P + p];
    }
    __syncthreads();
    #pragma unroll
    for (int r = 0; r < 16; r++) {
        int idx = t + 256*r;
        int k = idx >> 6, j = idx & 63;
        int i = j ^ k;
        int code = (__popc(i)&3)*16 + (__popc(j)&3)*4 + (__popc(k)&3);
        g_coef[n*4096 + idx] = g_sgnb[idx] * f4[code];
    }
}

// Setup C: pre-pack x into pad-swizzled pair layout. One block per b.
// word(co, par, mp) = mp*140 + co*2 + par + (co>>4)*4; value = x[b][2mp+par][c2s[co]].
__global__ void k_setup_xp(const float* __restrict__ x) {
    __shared__ float xs[8192];
    __shared__ int c2s[64];
    int b = blockIdx.x, t = threadIdx.x;
    if (t < 64) c2s[t] = g_c2s[t];
    #pragma unroll
    for (int r = 0; r < 32; r++) xs[t + 256*r] = x[(size_t)b*8192 + t + 256*r];
    __syncthreads();
    for (int w = t; w < 8960; w += 256) {
        int mp = w / 140, r = w % 140;
        int g = r / 36, rr = r % 36;
        float v = 0.f;
        if (rr < 32) {
            int co = g*16 + (rr >> 1), par = rr & 1;
            v = xs[(2*mp + par)*64 + c2s[co]];
        }
        g_xp[(size_t)b*8960 + w] = v;
    }
}

// Setup D: pre-pack w_lin into pair layout.
// g_wp[nt*16512 + mp*258 + slot*8 + c*2 + par] = w_lin[(nt*32+slot)*512 + (2mp+par)*4 + c]
__global__ void k_setup_wp(const float* __restrict__ w_lin) {
    int idx = blockIdx.x*256 + threadIdx.x;   // 258 blocks -> 66048
    int nt = idx / 16512, r1 = idx % 16512;
    int mp = r1 / 258, ww = r1 % 258;
    float v = 0.f;
    if (ww < 256) {
        int slot = ww >> 3, c = (ww >> 1) & 3, par = ww & 1;
        v = w_lin[(nt*32 + slot)*512 + (2*mp + par)*4 + c];
    }
    g_wp[idx] = v;
}

// ---------------------------------------------------------------------------
// Kernel 1: linear mix + bias + class-norm gate, f32x2 over m-pairs.
// grid 1024 = (b:256) x (nt:4 of 32 n), block 128.
// thread: ig = class-ordered blade quad (16), nh = n slot (8);
// handles n = nt*32 + nh + 8q for q=0..3.
// smem: Xp words [0, 8960); Wp words [8960, 25472).
__global__ __launch_bounds__(128) void k_linear(
    const float* __restrict__ b_lin, const float* __restrict__ a_norm) {
    extern __shared__ float sm[];
    __shared__ int sc2b[64], sq[16];
    int t = threadIdx.x;
    int b = blockIdx.x >> 2, nt = blockIdx.x & 3;
    if (t < 64) sc2b[t] = g_c2b[t];
    if (t < 16) sq[t] = g_qcls[t];

    const float4* xg = (const float4*)(g_xp + (size_t)b*8960);
    float4* xs4 = (float4*)sm;
    #pragma unroll
    for (int r = 0; r < 18; r++) {
        int idx = t + 128*r;
        if (idx < 2240) xs4[idx] = xg[idx];
    }
    const float4* wg = (const float4*)(g_wp + nt*16512);
    float4* ws4 = (float4*)(sm + 8960);
    #pragma unroll
    for (int r = 0; r < 32; r++) ws4[t + 128*r] = wg[t + 128*r];
    if (t < 32) ws4[t + 4096] = wg[t + 4096];
    __syncthreads();

    int ig = t & 15, nh = t >> 4;
    int c = sq[ig];
    const ulonglong2* px = (const ulonglong2*)sm + ig*2 + (ig >> 2);
    const u64t* pw = (const u64t*)(sm + 8960);
    int wo0 = (nh+ 0)*4 + c, wo1 = (nh+ 8)*4 + c;
    int wo2 = (nh+16)*4 + c, wo3 = (nh+24)*4 + c;

    u64t acc[4][4];
    #pragma unroll
    for (int q = 0; q < 4; q++)
        #pragma unroll
        for (int d = 0; d < 4; d++) acc[q][d] = 0ull;

    #pragma unroll 8
    for (int mp = 0; mp < 64; mp++) {
        ulonglong2 xa = px[mp*35];
        ulonglong2 xb = px[mp*35 + 1];
        u64t w0 = pw[mp*129 + wo0];
        u64t w1 = pw[mp*129 + wo1];
        u64t w2 = pw[mp*129 + wo2];
        u64t w3 = pw[mp*129 + wo3];
        FMA2(acc[0][0], xa.x, w0, acc[0][0]);
        FMA2(acc[0][1], xa.y, w0, acc[0][1]);
        FMA2(acc[0][2], xb.x, w0, acc[0][2]);
        FMA2(acc[0][3], xb.y, w0, acc[0][3]);
        FMA2(acc[1][0], xa.x, w1, acc[1][0]);
        FMA2(acc[1][1], xa.y, w1, acc[1][1]);
        FMA2(acc[1][2], xb.x, w1, acc[1][2]);
        FMA2(acc[1][3], xb.y, w1, acc[1][3]);
        FMA2(acc[2][0], xa.x, w2, acc[2][0]);
        FMA2(acc[2][1], xa.y, w2, acc[2][1]);
        FMA2(acc[2][2], xb.x, w2, acc[2][2]);
        FMA2(acc[2][3], xb.y, w2, acc[2][3]);
        FMA2(acc[3][0], xa.x, w3, acc[3][0]);
        FMA2(acc[3][1], xa.y, w3, acc[3][1]);
        FMA2(acc[3][2], xb.x, w3, acc[3][2]);
        FMA2(acc[3][3], xb.y, w3, acc[3][3]);
    }

    float f[4][4];
    #pragma unroll
    for (int q = 0; q < 4; q++)
        #pragma unroll
        for (int d = 0; d < 4; d++) {
            float lo, hi; UNPACK2(lo, hi, acc[q][d]);
            f[q][d] = lo + hi;
        }
    int nq[4];
    #pragma unroll
    for (int q = 0; q < 4; q++) nq[q] = nt*32 + nh + 8*q;
    if (ig == 0) {
        #pragma unroll
        for (int q = 0; q < 4; q++) f[q][0] += b_lin[nq[q]];
    }

    float v[4][4];
    #pragma unroll
    for (int q = 0; q < 4; q++) {
        float s = f[q][0]*f[q][0] + f[q][1]*f[q][1]
                + f[q][2]*f[q][2] + f[q][3]*f[q][3];
        #pragma unroll
        for (int cc = 0; cc < 4; cc++) v[q][cc] = (c == cc) ? s : 0.f;
    }
    #pragma unroll
    for (int off = 8; off; off >>= 1) {
        #pragma unroll
        for (int q = 0; q < 4; q++)
            #pragma unroll
            for (int cc = 0; cc < 4; cc++)
                v[q][cc] += __shfl_xor_sync(0xffffffffu, v[q][cc], off);
    }
    #pragma unroll
    for (int q = 0; q < 4; q++) {
        float vv = (c==0)?v[q][0]:(c==1)?v[q][1]:(c==2)?v[q][2]:v[q][3];
        float gg = 1.f/(1.f + expf(-a_norm[nq[q]*4 + c]));
        float inv = 1.f/(gg*(sqrtf(vv) - 1.f) + 1.f + EPS);
        float* o = g_xr + (size_t)b*8192 + (size_t)nq[q]*64;
        o[sc2b[ig*4+0]] = f[q][0]*inv;
        o[sc2b[ig*4+1]] = f[q][1]*inv;
        o[sc2b[ig*4+2]] = f[q][2]*inv;
        o[sc2b[ig*4+3]] = f[q][3]*inv;
    }
}

// ---------------------------------------------------------------------------
// Kernel 2: out[b,n,j] = sum_k coef[n][k][j] * x[b,n,j^k] * xr[b,n,k]
// f32x2 packed over batch pairs. grid (n:128, bg:4), block 256.
// warp = j-octet jo; lane = batch pair bp.
// smem words: Cs2 dup pairs [0, 8192); Rp [8192,12416): k*66+2*bp;
//             Xp [12416, 16640): i*66+2*bp.
__global__ __launch_bounds__(256, 3) void k_bilinear(
    const float* __restrict__ x, float* __restrict__ out) {
    extern __shared__ float sm[];
    __shared__ int sjb[64];
    int n = blockIdx.x, bg = blockIdx.y;
    int t = threadIdx.x;
    if (t < 64) sjb[t] = g_b2s[t];

    u64t* Cs2 = (u64t*)sm;
    #pragma unroll
    for (int r = 0; r < 16; r++) {
        int idx = t + 256*r;
        float c = g_coef[n*4096 + idx];
        u64t pc; PACK2(pc, c, c);
        Cs2[idx] = pc;
    }
    __syncthreads();   // sjb ready
    #pragma unroll
    for (int r = 0; r < 8; r++) {
        int p = t + 256*r;
        int i = p & 63, bq = p >> 6;
        size_t gb = (size_t)(bg*64 + 2*bq)*8192 + (size_t)n*64;
        int s = sjb[i];
        float xl = x[gb + s],      xh = x[gb + 8192 + s];
        float rl = g_xr[gb + i],   rh = g_xr[gb + 8192 + i];
        u64t pxv, prv; PACK2(pxv, xl, xh); PACK2(prv, rl, rh);
        *(u64t*)(sm + 12416 + i*66 + 2*bq) = pxv;
        *(u64t*)(sm + 8192  + i*66 + 2*bq) = prv;
    }
    __syncthreads();

    int lane = t & 31, jo = t >> 5;
    const u64t* pR = (const u64t*)sm + 4096 + lane;   // + k*33
    const u64t* pX = (const u64t*)sm + 6208 + lane;   // + i*33
    const ulonglong2* pC = (const ulonglong2*)sm;     // + k*32 + jo*4 + jp

    u64t acc[8];
    #pragma unroll
    for (int jj = 0; jj < 8; jj++) acc[jj] = 0ull;

    for (int ko = 0; ko < 8; ko++) {
        u64t rv[8], xv[8];
        #pragma unroll
        for (int kk = 0; kk < 8; kk++) rv[kk] = pR[(ko*8 + kk)*33];
        int io = jo ^ ko;
        #pragma unroll
        for (int d = 0; d < 8; d++) xv[d] = pX[(io*8 + d)*33];
        #pragma unroll
        for (int kk = 0; kk < 8; kk++) {
            const ulonglong2* pCk = pC + (ko*8 + kk)*32 + jo*4;
            #pragma unroll
            for (int jp = 0; jp < 4; jp++) {
                ulonglong2 cc = pCk[jp];
                u64t t0, t1;
                MUL2(t0, xv[(2*jp)^kk], rv[kk]);
                FMA2(acc[2*jp], cc.x, t0, acc[2*jp]);
                MUL2(t1, xv[(2*jp+1)^kk], rv[kk]);
                FMA2(acc[2*jp+1], cc.y, t1, acc[2*jp+1]);
            }
        }
    }
    __syncthreads();
    float* Os = sm;   // 64 rows x 68 floats, reuses Cs2 region
    #pragma unroll
    for (int jj = 0; jj < 8; jj++) {
        float lo, hi; UNPACK2(lo, hi, acc[jj]);
        int sjq = sjb[jo*8 + jj];
        Os[(2*lane)*68 + sjq]   = lo;
        Os[(2*lane+1)*68 + sjq] = hi;
    }
    __syncthreads();
    #pragma unroll
    for (int r = 0; r < 4; r++) {
        int idx = t + 256*r;
        int row = idx >> 4, c4 = idx & 15;
        float4 v = *(const float4*)(Os + row*68 + c4*4);
        *(float4*)(out + (size_t)(bg*64 + row)*8192 + (size_t)n*64 + c4*4) = v;
    }
}

// ---------------------------------------------------------------------------
extern "C" void kernel_launch(void* const* d_in, const int* in_sizes, int n_in,
                              void* d_out, int out_size) {
    const float* x      = (const float*)d_in[0];
    const float* w_gp   = (const float*)d_in[1];
    const float* w_lin  = (const float*)d_in[2];
    const float* b_lin  = (const float*)d_in[3];
    const float* a_norm = (const float*)d_in[4];
    const float* cayley = (const float*)d_in[5];
    const int*   pidx   = (const int*)d_in[7];
    int P = in_sizes[7] / 3;
    float* out = (float*)d_out;
    (void)n_in; (void)out_size;

    cudaFuncSetAttribute(k_linear,   cudaFuncAttributeMaxDynamicSharedMemorySize, 25472*4);
    cudaFuncSetAttribute(k_bilinear, cudaFuncAttributeMaxDynamicSharedMemorySize, 16640*4);

    k_setup_tables<<<16, 256>>>(cayley);
    k_setup_coef<<<128, 256>>>(w_gp, pidx, P);
    k_setup_xp<<<256, 256>>>(x);
    k_setup_wp<<<258, 256>>>(w_lin);
    k_linear<<<1024, 128, 25472*4>>>(b_lin, a_norm);
    k_bilinear<<<dim3(128, 4), 256, 16640*4>>>(x, out);
}

// round 7
// speedup vs baseline: 1.2314x; 1.2314x over previous
#include <cuda_runtime.h>

#define EPS 1e-6f
typedef unsigned long long u64t;

#define MUL2(d,a,b)    asm("mul.rn.f32x2 %0, %1, %2;" : "=l"(d) : "l"(a), "l"(b))
#define FMA2(d,a,b,c)  asm("fma.rn.f32x2 %0, %1, %2, %3;" : "=l"(d) : "l"(a), "l"(b), "l"(c))
#define PACK2(d,lo,hi) asm("mov.b64 %0, {%1, %2};" : "=l"(d) : "f"(lo), "f"(hi))
#define UNPACK2(lo,hi,s) asm("mov.b64 {%0, %1}, %2;" : "=f"(lo), "=f"(hi) : "l"(s))

// Scratch (device globals: no allocation allowed)
__device__ float g_xr[256*128*64];     // xr in BINARY blade order, 8 MB
__device__ float g_coef[128*64*64];    // coef[n][k_bin][j_bin], 2 MB
__device__ float g_wp[4*16512];        // w pre-packed pair layout, 264 KB
__device__ int   g_b2s[64];            // binary blade -> sorted index
__device__ int   g_s2c[64];            // sorted index -> class-order pos
__device__ int   g_c2b[64];            // class-order pos -> binary blade
__device__ int   g_qcls[16];           // class per class-order quad

// ---------------------------------------------------------------------------
// Fused setup. grid 133 x 256.
// block 0:        blade-order tables
// blocks 1-128:   coef for n = blk-1 (Cayley sign computed via popc, no input)
// blocks 129-132: w_lin pre-pack for nt = blk-129 (smem-staged, coalesced)
__global__ void k_setup(const float* __restrict__ w_gp,
                        const int* __restrict__ pidx, int P,
                        const float* __restrict__ w_lin) {
    extern __shared__ float smem[];
    int blk = blockIdx.x, t = threadIdx.x;

    if (blk == 0) {
        __shared__ int s_of_b[64];
        if (t < 64) {
            int pc = __popc(t), rank = 0;
            for (int u = 0; u < 64; u++) {
                int pu = __popc(u);
                rank += (pu < pc) || (pu == pc && u < t);
            }
            s_of_b[t] = rank;
            g_b2s[t] = rank;
        }
        __syncthreads();
        if (t < 64) {
            int c = __popc(t) & 3;
            int s = s_of_b[t];
            int co = 0;
            for (int u = 0; u < 64; u++) {
                int cu = __popc(u) & 3;
                co += (cu < c) || (cu == c && s_of_b[u] < s);
            }
            g_s2c[s] = co;
            g_c2b[co] = t;
            if ((co & 3) == 0) g_qcls[co >> 2] = c;
        }
    } else if (blk <= 128) {
        int n = blk - 1;
        __shared__ float f4[64];
        if (t < 64) f4[t] = 0.f;
        __syncthreads();
        for (int p = t; p < P; p += 256) {
            int code = pidx[3*p]*16 + pidx[3*p+1]*4 + pidx[3*p+2];
            f4[code] = w_gp[n*P + p];
        }
        __syncthreads();
        #pragma unroll
        for (int r = 0; r < 16; r++) {
            int idx = t + 256*r;
            int k = idx >> 6, j = idx & 63, i = j ^ k;
            // swap_sign(i, k)
            int a = i >> 1, s = 0;
            while (a) { s += __popc(a & k); a >>= 1; }
            float sgn = (s & 1) ? -1.f : 1.f;
            int code = (__popc(i)&3)*16 + (__popc(j)&3)*4 + (__popc(k)&3);
            g_coef[n*4096 + idx] = sgn * f4[code];
        }
    } else {
        int nt = blk - 129;
        const float4* wg4 = (const float4*)(w_lin + nt*16384);
        float4* s4 = (float4*)smem;
        #pragma unroll
        for (int r = 0; r < 16; r++) s4[t + 256*r] = wg4[t + 256*r];
        __syncthreads();
        for (int w = t; w < 16512; w += 256) {
            int mp = w / 258, ww = w % 258;
            float v = 0.f;
            if (ww < 256) {
                int slot = ww >> 3, c = (ww >> 1) & 3, par = ww & 1;
                v = smem[slot*512 + (2*mp + par)*4 + c];
            }
            g_wp[nt*16512 + w] = v;
        }
    }
}

// ---------------------------------------------------------------------------
// Kernel 1: linear mix + bias + class-norm gate, f32x2 over m-pairs.
// grid 1024 = (b:256) x (nt:4 of 32 n), block 256 (in-kernel x transpose).
// thread: ig = class-ordered blade quad (16), nh = (t>>4)&7, qh = t>>7;
// handles n0 = nt*32 + nh + 16*qh and n1 = n0 + 8.
// smem: Xp words [0, 8960): mp*140 + co*2 + par + (co>>4)*4
//       Wp words [8960, 25472): mp*258 + slot*8 + c*2 + par    (102 KB total)
__global__ __launch_bounds__(256, 2) void k_linear(
    const float* __restrict__ x, const float* __restrict__ b_lin,
    const float* __restrict__ a_norm) {
    extern __shared__ float sm[];
    __shared__ int ss2c[64], sc2b[64], sq[16];
    int t = threadIdx.x;
    int b = blockIdx.x >> 2, nt = blockIdx.x & 3;
    if (t < 64) { ss2c[t] = g_s2c[t]; sc2b[t] = g_c2b[t]; }
    if (t >= 64 && t < 80) sq[t - 64] = g_qcls[t - 64];
    __syncthreads();   // ss2c needed for staging

    // stage x with class-sort + pad-swizzle transpose
    {
        const float4* xg = (const float4*)(x + (size_t)b*8192);
        #pragma unroll
        for (int r = 0; r < 8; r++) {
            int idx4 = t + 256*r;
            float4 v = xg[idx4];
            int m = idx4 >> 4, s0 = (idx4 & 15)*4;
            int mp = m >> 1, par = m & 1;
            int co;
            co = ss2c[s0+0]; sm[mp*140 + co*2 + par + ((co>>4)<<2)] = v.x;
            co = ss2c[s0+1]; sm[mp*140 + co*2 + par + ((co>>4)<<2)] = v.y;
            co = ss2c[s0+2]; sm[mp*140 + co*2 + par + ((co>>4)<<2)] = v.z;
            co = ss2c[s0+3]; sm[mp*140 + co*2 + par + ((co>>4)<<2)] = v.w;
        }
    }
    // stage pre-packed w
    {
        const float4* wg = (const float4*)(g_wp + nt*16512);
        float4* ws4 = (float4*)(sm + 8960);
        #pragma unroll
        for (int r = 0; r < 16; r++) ws4[t + 256*r] = wg[t + 256*r];
        if (t < 32) ws4[t + 4096] = wg[t + 4096];
    }
    __syncthreads();

    int ig = t & 15, nh = (t >> 4) & 7, qh = t >> 7;
    int c = sq[ig];
    const ulonglong2* px = (const ulonglong2*)sm + ig*2 + (ig >> 2);
    const u64t* pw = (const u64t*)(sm + 8960);
    int wo0 = (nh + 16*qh)*4 + c;
    int wo1 = (nh + 16*qh + 8)*4 + c;

    u64t acc[2][4];
    #pragma unroll
    for (int q = 0; q < 2; q++)
        #pragma unroll
        for (int d = 0; d < 4; d++) acc[q][d] = 0ull;

    #pragma unroll 8
    for (int mp = 0; mp < 64; mp++) {
        ulonglong2 xa = px[mp*35];
        ulonglong2 xb = px[mp*35 + 1];
        u64t w0 = pw[mp*129 + wo0];
        u64t w1 = pw[mp*129 + wo1];
        FMA2(acc[0][0], xa.x, w0, acc[0][0]);
        FMA2(acc[0][1], xa.y, w0, acc[0][1]);
        FMA2(acc[0][2], xb.x, w0, acc[0][2]);
        FMA2(acc[0][3], xb.y, w0, acc[0][3]);
        FMA2(acc[1][0], xa.x, w1, acc[1][0]);
        FMA2(acc[1][1], xa.y, w1, acc[1][1]);
        FMA2(acc[1][2], xb.x, w1, acc[1][2]);
        FMA2(acc[1][3], xb.y, w1, acc[1][3]);
    }

    float f[2][4];
    #pragma unroll
    for (int q = 0; q < 2; q++)
        #pragma unroll
        for (int d = 0; d < 4; d++) {
            float lo, hi; UNPACK2(lo, hi, acc[q][d]);
            f[q][d] = lo + hi;
        }
    int n0 = nt*32 + nh + 16*qh;
    if (ig == 0) { f[0][0] += b_lin[n0]; f[1][0] += b_lin[n0 + 8]; }

    float v[2][4];
    #pragma unroll
    for (int q = 0; q < 2; q++) {
        float s = f[q][0]*f[q][0] + f[q][1]*f[q][1]
                + f[q][2]*f[q][2] + f[q][3]*f[q][3];
        #pragma unroll
        for (int cc = 0; cc < 4; cc++) v[q][cc] = (c == cc) ? s : 0.f;
    }
    #pragma unroll
    for (int off = 8; off; off >>= 1) {
        #pragma unroll
        for (int q = 0; q < 2; q++)
            #pragma unroll
            for (int cc = 0; cc < 4; cc++)
                v[q][cc] += __shfl_xor_sync(0xffffffffu, v[q][cc], off);
    }
    #pragma unroll
    for (int q = 0; q < 2; q++) {
        int n = n0 + 8*q;
        float vv = (c==0)?v[q][0]:(c==1)?v[q][1]:(c==2)?v[q][2]:v[q][3];
        float gg = 1.f/(1.f + expf(-a_norm[n*4 + c]));
        float inv = 1.f/(gg*(sqrtf(vv) - 1.f) + 1.f + EPS);
        float* o = g_xr + (size_t)b*8192 + (size_t)n*64;
        o[sc2b[ig*4+0]] = f[q][0]*inv;
        o[sc2b[ig*4+1]] = f[q][1]*inv;
        o[sc2b[ig*4+2]] = f[q][2]*inv;
        o[sc2b[ig*4+3]] = f[q][3]*inv;
    }
}

// ---------------------------------------------------------------------------
// Kernel 2: out[b,n,j] = sum_k coef[n][k][j] * x[b,n,j^k] * xr[b,n,k]
// f32x2 packed over batch pairs. grid (n:128, bg:4), block 256.
// warp = j-octet jo; lane = batch pair bp.
// smem words: Cs2 dup pairs [0, 8192); Rp [8192,12416): k*66+2*bp;
//             Xp [12416, 16640): i*66+2*bp.
__global__ __launch_bounds__(256, 3) void k_bilinear(
    const float* __restrict__ x, float* __restrict__ out) {
    extern __shared__ float sm[];
    __shared__ int sjb[64];
    int n = blockIdx.x, bg = blockIdx.y;
    int t = threadIdx.x;
    if (t < 64) sjb[t] = g_b2s[t];

    u64t* Cs2 = (u64t*)sm;
    #pragma unroll
    for (int r = 0; r < 16; r++) {
        int idx = t + 256*r;
        float c = g_coef[n*4096 + idx];
        u64t pc; PACK2(pc, c, c);
        Cs2[idx] = pc;
    }
    __syncthreads();   // sjb ready
    #pragma unroll
    for (int r = 0; r < 8; r++) {
        int p = t + 256*r;
        int i = p & 63, bq = p >> 6;
        size_t gb = (size_t)(bg*64 + 2*bq)*8192 + (size_t)n*64;
        int s = sjb[i];
        float xl = x[gb + s],      xh = x[gb + 8192 + s];
        float rl = g_xr[gb + i],   rh = g_xr[gb + 8192 + i];
        u64t pxv, prv; PACK2(pxv, xl, xh); PACK2(prv, rl, rh);
        *(u64t*)(sm + 12416 + i*66 + 2*bq) = pxv;
        *(u64t*)(sm + 8192  + i*66 + 2*bq) = prv;
    }
    __syncthreads();

    int lane = t & 31, jo = t >> 5;
    const u64t* pR = (const u64t*)sm + 4096 + lane;   // + k*33
    const u64t* pX = (const u64t*)sm + 6208 + lane;   // + i*33
    const ulonglong2* pC = (const ulonglong2*)sm;     // + k*32 + jo*4 + jp

    u64t acc[8];
    #pragma unroll
    for (int jj = 0; jj < 8; jj++) acc[jj] = 0ull;

    for (int ko = 0; ko < 8; ko++) {
        u64t rv[8], xv[8];
        #pragma unroll
        for (int kk = 0; kk < 8; kk++) rv[kk] = pR[(ko*8 + kk)*33];
        int io = jo ^ ko;
        #pragma unroll
        for (int d = 0; d < 8; d++) xv[d] = pX[(io*8 + d)*33];
        #pragma unroll
        for (int kk = 0; kk < 8; kk++) {
            const ulonglong2* pCk = pC + (ko*8 + kk)*32 + jo*4;
            #pragma unroll
            for (int jp = 0; jp < 4; jp++) {
                ulonglong2 cc = pCk[jp];
                u64t t0, t1;
                MUL2(t0, xv[(2*jp)^kk], rv[kk]);
                FMA2(acc[2*jp], cc.x, t0, acc[2*jp]);
                MUL2(t1, xv[(2*jp+1)^kk], rv[kk]);
                FMA2(acc[2*jp+1], cc.y, t1, acc[2*jp+1]);
            }
        }
    }
    __syncthreads();
    float* Os = sm;   // 64 rows x 68 floats, reuses Cs2 region
    #pragma unroll
    for (int jj = 0; jj < 8; jj++) {
        float lo, hi; UNPACK2(lo, hi, acc[jj]);
        int sjq = sjb[jo*8 + jj];
        Os[(2*lane)*68 + sjq]   = lo;
        Os[(2*lane+1)*68 + sjq] = hi;
    }
    __syncthreads();
    #pragma unroll
    for (int r = 0; r < 4; r++) {
        int idx = t + 256*r;
        int row = idx >> 4, c4 = idx & 15;
        float4 v = *(const float4*)(Os + row*68 + c4*4);
        *(float4*)(out + (size_t)(bg*64 + row)*8192 + (size_t)n*64 + c4*4) = v;
    }
}

// ---------------------------------------------------------------------------
extern "C" void kernel_launch(void* const* d_in, const int* in_sizes, int n_in,
                              void* d_out, int out_size) {
    const float* x      = (const float*)d_in[0];
    const float* w_gp   = (const float*)d_in[1];
    const float* w_lin  = (const float*)d_in[2];
    const float* b_lin  = (const float*)d_in[3];
    const float* a_norm = (const float*)d_in[4];
    const int*   pidx   = (const int*)d_in[7];
    int P = in_sizes[7] / 3;
    float* out = (float*)d_out;
    (void)n_in; (void)out_size;

    cudaFuncSetAttribute(k_setup,    cudaFuncAttributeMaxDynamicSharedMemorySize, 65536);
    cudaFuncSetAttribute(k_linear,   cudaFuncAttributeMaxDynamicSharedMemorySize, 25472*4);
    cudaFuncSetAttribute(k_bilinear, cudaFuncAttributeMaxDynamicSharedMemorySize, 16640*4);

    k_setup<<<133, 256, 65536>>>(w_gp, pidx, P, w_lin);
    k_linear<<<1024, 256, 25472*4>>>(x, b_lin, a_norm);
    k_bilinear<<<dim3(128, 4), 256, 16640*4>>>(x, out);
}

// round 8
// speedup vs baseline: 1.3193x; 1.0714x over previous
#include <cuda_runtime.h>

#define EPS 1e-6f
typedef unsigned long long u64t;

#define MUL2(d,a,b)    asm("mul.rn.f32x2 %0, %1, %2;" : "=l"(d) : "l"(a), "l"(b))
#define FMA2(d,a,b,c)  asm("fma.rn.f32x2 %0, %1, %2, %3;" : "=l"(d) : "l"(a), "l"(b), "l"(c))
#define PACK2(d,lo,hi) asm("mov.b64 %0, {%1, %2};" : "=l"(d) : "f"(lo), "f"(hi))
#define UNPACK2(lo,hi,s) asm("mov.b64 {%0, %1}, %2;" : "=f"(lo), "=f"(hi) : "l"(s))

// Scratch (device global: no allocation allowed)
__device__ float g_xr[256*128*64];     // xr in BINARY blade order, 8 MB

// ---------------------------------------------------------------------------
// Compile-time blade-ordering tables (input-independent, N_GEN=6 fixed).
struct Tab { int b2s[64]; int s2c[64]; int c2b[64]; int qcls[16]; };

constexpr int popc_c(int v) { int c = 0; while (v) { c += v & 1; v >>= 1; } return c; }

constexpr Tab make_tab() {
    Tab T{};
    int s_of_b[64] = {};
    for (int b = 0; b < 64; b++) {
        int pc = popc_c(b), rank = 0;
        for (int u = 0; u < 64; u++) {
            int pu = popc_c(u);
            if (pu < pc || (pu == pc && u < b)) rank++;
        }
        s_of_b[b] = rank;
        T.b2s[b] = rank;
    }
    for (int b = 0; b < 64; b++) {
        int c = popc_c(b) & 3, s = s_of_b[b], co = 0;
        for (int u = 0; u < 64; u++) {
            int cu = popc_c(u) & 3;
            if (cu < c || (cu == c && s_of_b[u] < s)) co++;
        }
        T.s2c[s] = co;
        T.c2b[co] = b;
        if ((co & 3) == 0) T.qcls[co >> 2] = c;
    }
    return T;
}

__constant__ Tab d_tab = make_tab();

// ---------------------------------------------------------------------------
// Kernel 1: linear mix + bias + class-norm gate, f32x2 over m-pairs.
// grid 1024 = (b:256) x (nt:4 of 32 n), block 256.
// In-kernel staging: x class-sorted pad-swizzled transpose; w repacked
// directly from w_lin (conflict-free scattered STS).
// thread: ig = class-ordered blade quad (16), nh = (t>>4)&7, qh = t>>7;
// handles n0 = nt*32 + nh + 16*qh and n1 = n0 + 8.
// smem: Xp words [0, 8960): mp*140 + co*2 + par + (co>>4)*4
//       Wp words [8960, 25472): mp*258 + slot*8 + c*2 + par    (102 KB total)
__global__ __launch_bounds__(256, 2) void k_linear(
    const float* __restrict__ x, const float* __restrict__ w_lin,
    const float* __restrict__ b_lin, const float* __restrict__ a_norm) {
    extern __shared__ float sm[];
    __shared__ int ss2c[64], sc2b[64], sq[16];
    int t = threadIdx.x;
    int b = blockIdx.x >> 2, nt = blockIdx.x & 3;
    if (t < 64) { ss2c[t] = d_tab.s2c[t]; sc2b[t] = d_tab.c2b[t]; }
    if (t >= 64 && t < 80) sq[t - 64] = d_tab.qcls[t - 64];
    __syncthreads();   // ss2c needed for staging

    // stage x with class-sort + pad-swizzle transpose
    {
        const float4* xg = (const float4*)(x + (size_t)b*8192);
        #pragma unroll
        for (int r = 0; r < 8; r++) {
            int idx4 = t + 256*r;
            float4 v = xg[idx4];
            int m = idx4 >> 4, s0 = (idx4 & 15)*4;
            int mp = m >> 1, par = m & 1;
            int co;
            co = ss2c[s0+0]; sm[mp*140 + co*2 + par + ((co>>4)<<2)] = v.x;
            co = ss2c[s0+1]; sm[mp*140 + co*2 + par + ((co>>4)<<2)] = v.y;
            co = ss2c[s0+2]; sm[mp*140 + co*2 + par + ((co>>4)<<2)] = v.z;
            co = ss2c[s0+3]; sm[mp*140 + co*2 + par + ((co>>4)<<2)] = v.w;
        }
    }
    // stage w directly from w_lin with pair repack
    {
        const float4* wg4 = (const float4*)(w_lin + nt*32*512);
        #pragma unroll
        for (int r = 0; r < 16; r++) {
            int idx4 = t + 256*r;              // 4096 float4
            float4 v = wg4[idx4];
            int slot = idx4 >> 7, m = idx4 & 127;
            int base = 8960 + (m >> 1)*258 + slot*8 + (m & 1);
            sm[base + 0] = v.x;
            sm[base + 2] = v.y;
            sm[base + 4] = v.z;
            sm[base + 6] = v.w;
        }
    }
    __syncthreads();

    int ig = t & 15, nh = (t >> 4) & 7, qh = t >> 7;
    int c = sq[ig];
    const ulonglong2* px = (const ulonglong2*)sm + ig*2 + (ig >> 2);
    const u64t* pw = (const u64t*)(sm + 8960);
    int wo0 = (nh + 16*qh)*4 + c;
    int wo1 = (nh + 16*qh + 8)*4 + c;

    u64t acc[2][4];
    #pragma unroll
    for (int q = 0; q < 2; q++)
        #pragma unroll
        for (int d = 0; d < 4; d++) acc[q][d] = 0ull;

    #pragma unroll 8
    for (int mp = 0; mp < 64; mp++) {
        ulonglong2 xa = px[mp*35];
        ulonglong2 xb = px[mp*35 + 1];
        u64t w0 = pw[mp*129 + wo0];
        u64t w1 = pw[mp*129 + wo1];
        FMA2(acc[0][0], xa.x, w0, acc[0][0]);
        FMA2(acc[0][1], xa.y, w0, acc[0][1]);
        FMA2(acc[0][2], xb.x, w0, acc[0][2]);
        FMA2(acc[0][3], xb.y, w0, acc[0][3]);
        FMA2(acc[1][0], xa.x, w1, acc[1][0]);
        FMA2(acc[1][1], xa.y, w1, acc[1][1]);
        FMA2(acc[1][2], xb.x, w1, acc[1][2]);
        FMA2(acc[1][3], xb.y, w1, acc[1][3]);
    }

    float f[2][4];
    #pragma unroll
    for (int q = 0; q < 2; q++)
        #pragma unroll
        for (int d = 0; d < 4; d++) {
            float lo, hi; UNPACK2(lo, hi, acc[q][d]);
            f[q][d] = lo + hi;
        }
    int n0 = nt*32 + nh + 16*qh;
    if (ig == 0) { f[0][0] += b_lin[n0]; f[1][0] += b_lin[n0 + 8]; }

    float v[2][4];
    #pragma unroll
    for (int q = 0; q < 2; q++) {
        float s = f[q][0]*f[q][0] + f[q][1]*f[q][1]
                + f[q][2]*f[q][2] + f[q][3]*f[q][3];
        #pragma unroll
        for (int cc = 0; cc < 4; cc++) v[q][cc] = (c == cc) ? s : 0.f;
    }
    #pragma unroll
    for (int off = 8; off; off >>= 1) {
        #pragma unroll
        for (int q = 0; q < 2; q++)
            #pragma unroll
            for (int cc = 0; cc < 4; cc++)
                v[q][cc] += __shfl_xor_sync(0xffffffffu, v[q][cc], off);
    }
    #pragma unroll
    for (int q = 0; q < 2; q++) {
        int n = n0 + 8*q;
        float vv = (c==0)?v[q][0]:(c==1)?v[q][1]:(c==2)?v[q][2]:v[q][3];
        float gg = 1.f/(1.f + expf(-a_norm[n*4 + c]));
        float inv = 1.f/(gg*(sqrtf(vv) - 1.f) + 1.f + EPS);
        float* o = g_xr + (size_t)b*8192 + (size_t)n*64;
        o[sc2b[ig*4+0]] = f[q][0]*inv;
        o[sc2b[ig*4+1]] = f[q][1]*inv;
        o[sc2b[ig*4+2]] = f[q][2]*inv;
        o[sc2b[ig*4+3]] = f[q][3]*inv;
    }
}

// ---------------------------------------------------------------------------
// Kernel 2: out[b,n,j] = sum_k coef[n][k][j] * x[b,n,j^k] * xr[b,n,k]
// coef computed IN-KERNEL: sgn via O(1) parity formula, f4 from w_gp/pidx.
// f32x2 packed over batch pairs. grid (n:128, bg:4), block 256.
// warp = j-octet jo; lane = batch pair bp.
// smem words: Cs2 dup pairs [0, 8192); Rp [8192,12416): k*66+2*bp;
//             Xp [12416, 16640): i*66+2*bp.
__global__ __launch_bounds__(256, 3) void k_bilinear(
    const float* __restrict__ x, const float* __restrict__ w_gp,
    const int* __restrict__ pidx, int P, float* __restrict__ out) {
    extern __shared__ float sm[];
    __shared__ int sjb[64];
    __shared__ float f4[64];
    int n = blockIdx.x, bg = blockIdx.y;
    int t = threadIdx.x;
    if (t < 64) { sjb[t] = d_tab.b2s[t]; f4[t] = 0.f; }
    __syncthreads();

    // fill f4 from paths + stage x/xr (sjb ready)
    for (int p = t; p < P; p += 256) {
        int code = pidx[3*p]*16 + pidx[3*p+1]*4 + pidx[3*p+2];
        f4[code] = w_gp[n*P + p];
    }
    #pragma unroll
    for (int r = 0; r < 8; r++) {
        int p = t + 256*r;
        int i = p & 63, bq = p >> 6;
        size_t gb = (size_t)(bg*64 + 2*bq)*8192 + (size_t)n*64;
        int s = sjb[i];
        float xl = x[gb + s],      xh = x[gb + 8192 + s];
        float rl = g_xr[gb + i],   rh = g_xr[gb + 8192 + i];
        u64t pxv, prv; PACK2(pxv, xl, xh); PACK2(prv, rl, rh);
        *(u64t*)(sm + 12416 + i*66 + 2*bq) = pxv;
        *(u64t*)(sm + 8192  + i*66 + 2*bq) = prv;
    }
    __syncthreads();

    // compute coef dup-pairs in place (reads f4, writes [0,8192))
    u64t* Cs2 = (u64t*)sm;
    #pragma unroll
    for (int r = 0; r < 16; r++) {
        int idx = t + 256*r;
        int k = idx >> 6, j = idx & 63, i = j ^ k;
        int h = (i>>1) ^ (i>>2) ^ (i>>3) ^ (i>>4) ^ (i>>5);
        float sgn = (__popc(h & k) & 1) ? -1.f : 1.f;
        int code = (__popc(i)&3)*16 + (__popc(j)&3)*4 + (__popc(k)&3);
        float c = sgn * f4[code];
        u64t pc; PACK2(pc, c, c);
        Cs2[idx] = pc;
    }
    __syncthreads();

    int lane = t & 31, jo = t >> 5;
    const u64t* pR = (const u64t*)sm + 4096 + lane;   // + k*33
    const u64t* pX = (const u64t*)sm + 6208 + lane;   // + i*33
    const ulonglong2* pC = (const ulonglong2*)sm;     // + k*32 + jo*4 + jp

    u64t acc[8];
    #pragma unroll
    for (int jj = 0; jj < 8; jj++) acc[jj] = 0ull;

    for (int ko = 0; ko < 8; ko++) {
        u64t rv[8], xv[8];
        #pragma unroll
        for (int kk = 0; kk < 8; kk++) rv[kk] = pR[(ko*8 + kk)*33];
        int io = jo ^ ko;
        #pragma unroll
        for (int d = 0; d < 8; d++) xv[d] = pX[(io*8 + d)*33];
        #pragma unroll
        for (int kk = 0; kk < 8; kk++) {
            const ulonglong2* pCk = pC + (ko*8 + kk)*32 + jo*4;
            #pragma unroll
            for (int jp = 0; jp < 4; jp++) {
                ulonglong2 cc = pCk[jp];
                u64t t0, t1;
                MUL2(t0, xv[(2*jp)^kk], rv[kk]);
                FMA2(acc[2*jp], cc.x, t0, acc[2*jp]);
                MUL2(t1, xv[(2*jp+1)^kk], rv[kk]);
                FMA2(acc[2*jp+1], cc.y, t1, acc[2*jp+1]);
            }
        }
    }
    __syncthreads();
    float* Os = sm;   // 64 rows x 68 floats, reuses Cs2 region
    #pragma unroll
    for (int jj = 0; jj < 8; jj++) {
        float lo, hi; UNPACK2(lo, hi, acc[jj]);
        int sjq = sjb[jo*8 + jj];
        Os[(2*lane)*68 + sjq]   = lo;
        Os[(2*lane+1)*68 + sjq] = hi;
    }
    __syncthreads();
    #pragma unroll
    for (int r = 0; r < 4; r++) {
        int idx = t + 256*r;
        int row = idx >> 4, c4 = idx & 15;
        float4 v = *(const float4*)(Os + row*68 + c4*4);
        *(float4*)(out + (size_t)(bg*64 + row)*8192 + (size_t)n*64 + c4*4) = v;
    }
}

// ---------------------------------------------------------------------------
extern "C" void kernel_launch(void* const* d_in, const int* in_sizes, int n_in,
                              void* d_out, int out_size) {
    const float* x      = (const float*)d_in[0];
    const float* w_gp   = (const float*)d_in[1];
    const float* w_lin  = (const float*)d_in[2];
    const float* b_lin  = (const float*)d_in[3];
    const float* a_norm = (const float*)d_in[4];
    const int*   pidx   = (const int*)d_in[7];
    int P = in_sizes[7] / 3;
    float* out = (float*)d_out;
    (void)n_in; (void)out_size;

    cudaFuncSetAttribute(k_linear,   cudaFuncAttributeMaxDynamicSharedMemorySize, 25472*4);
    cudaFuncSetAttribute(k_bilinear, cudaFuncAttributeMaxDynamicSharedMemorySize, 16640*4);

    k_linear<<<1024, 256, 25472*4>>>(x, w_lin, b_lin, a_norm);
    k_bilinear<<<dim3(128, 4), 256, 16640*4>>>(x, w_gp, pidx, P, out);
}

// round 9
// speedup vs baseline: 1.4065x; 1.0661x over previous
#include <cuda_runtime.h>

#define EPS 1e-6f
typedef unsigned long long u64t;

#define MUL2(d,a,b)    asm("mul.rn.f32x2 %0, %1, %2;" : "=l"(d) : "l"(a), "l"(b))
#define FMA2(d,a,b,c)  asm("fma.rn.f32x2 %0, %1, %2, %3;" : "=l"(d) : "l"(a), "l"(b), "l"(c))
#define PACK2(d,lo,hi) asm("mov.b64 %0, {%1, %2};" : "=l"(d) : "f"(lo), "f"(hi))
#define UNPACK2(lo,hi,s) asm("mov.b64 {%0, %1}, %2;" : "=f"(lo), "=f"(hi) : "l"(s))

// Scratch (device globals: no allocation allowed)
__device__ float g_xr[256*128*64];     // xr in BINARY blade order, 8 MB
__device__ float g_wp[65536];          // w packed for LDG.64 streaming, 256 KB

// ---------------------------------------------------------------------------
// Compile-time blade-ordering tables (input-independent, N_GEN=6 fixed).
struct Tab { int b2s[64]; int s2c[64]; int c2b[64]; int qcls[16]; };

constexpr int popc_c(int v) { int c = 0; while (v) { c += v & 1; v >>= 1; } return c; }

constexpr Tab make_tab() {
    Tab T{};
    int s_of_b[64] = {};
    for (int b = 0; b < 64; b++) {
        int pc = popc_c(b), rank = 0;
        for (int u = 0; u < 64; u++) {
            int pu = popc_c(u);
            if (pu < pc || (pu == pc && u < b)) rank++;
        }
        s_of_b[b] = rank;
        T.b2s[b] = rank;
    }
    for (int b = 0; b < 64; b++) {
        int c = popc_c(b) & 3, s = s_of_b[b], co = 0;
        for (int u = 0; u < 64; u++) {
            int cu = popc_c(u) & 3;
            if (cu < c || (cu == c && s_of_b[u] < s)) co++;
        }
        T.s2c[s] = co;
        T.c2b[co] = b;
        if ((co & 3) == 0) T.qcls[co >> 2] = c;
    }
    return T;
}

__constant__ Tab d_tab = make_tab();

// ---------------------------------------------------------------------------
// Pack w_lin for LDG.64 streaming:
// g_wp[nt*16384 + mp*256 + slot*8 + c*2 + par] = w_lin[(nt*32+slot)*512 + (2mp+par)*4 + c]
__global__ void k_wpack(const float* __restrict__ w_lin) {
    int idx = blockIdx.x*256 + threadIdx.x;          // 65536
    int n = idx >> 9, rem = idx & 511;
    int m = rem >> 2, c = rem & 3;
    g_wp[(n >> 5)*16384 + (m >> 1)*256 + (n & 31)*8 + c*2 + (m & 1)] = w_lin[idx];
}

// ---------------------------------------------------------------------------
// Kernel 1: linear mix + bias + class-norm gate, f32x2 over m-pairs.
// grid 1024 = (b:256) x (nt:4 of 32 n), block 256.
// x staged in smem (class-sorted pad-swizzle); w STREAMED from g_wp via
// LDG.64 (lanes 0-15 share a 32B sector). smem = x only -> 4 blocks/SM.
__global__ __launch_bounds__(256, 4) void k_linear(
    const float* __restrict__ x, const float* __restrict__ b_lin,
    const float* __restrict__ a_norm) {
    extern __shared__ float sm[];
    __shared__ int ss2c[64], sc2b[64], sq[16];
    int t = threadIdx.x;
    int b = blockIdx.x >> 2, nt = blockIdx.x & 3;
    if (t < 64) { ss2c[t] = d_tab.s2c[t]; sc2b[t] = d_tab.c2b[t]; }
    if (t >= 64 && t < 80) sq[t - 64] = d_tab.qcls[t - 64];
    __syncthreads();   // ss2c needed for staging

    // stage x with class-sort + pad-swizzle transpose
    {
        const float4* xg = (const float4*)(x + (size_t)b*8192);
        #pragma unroll
        for (int r = 0; r < 8; r++) {
            int idx4 = t + 256*r;
            float4 v = xg[idx4];
            int m = idx4 >> 4, s0 = (idx4 & 15)*4;
            int mp = m >> 1, par = m & 1;
            int co;
            co = ss2c[s0+0]; sm[mp*140 + co*2 + par + ((co>>4)<<2)] = v.x;
            co = ss2c[s0+1]; sm[mp*140 + co*2 + par + ((co>>4)<<2)] = v.y;
            co = ss2c[s0+2]; sm[mp*140 + co*2 + par + ((co>>4)<<2)] = v.z;
            co = ss2c[s0+3]; sm[mp*140 + co*2 + par + ((co>>4)<<2)] = v.w;
        }
    }
    __syncthreads();

    int ig = t & 15, nh = (t >> 4) & 7, qh = t >> 7;
    int c = sq[ig];
    const ulonglong2* px = (const ulonglong2*)sm + ig*2 + (ig >> 2);
    const u64t* gw = (const u64t*)g_wp + nt*8192;
    int wo0 = (nh + 16*qh)*4 + c;
    int wo1 = wo0 + 32;                 // slot + 8

    u64t acc[2][4];
    #pragma unroll
    for (int q = 0; q < 2; q++)
        #pragma unroll
        for (int d = 0; d < 4; d++) acc[q][d] = 0ull;

    #pragma unroll 8
    for (int mp = 0; mp < 64; mp++) {
        ulonglong2 xa = px[mp*35];
        ulonglong2 xb = px[mp*35 + 1];
        u64t w0 = gw[mp*128 + wo0];
        u64t w1 = gw[mp*128 + wo1];
        FMA2(acc[0][0], xa.x, w0, acc[0][0]);
        FMA2(acc[0][1], xa.y, w0, acc[0][1]);
        FMA2(acc[0][2], xb.x, w0, acc[0][2]);
        FMA2(acc[0][3], xb.y, w0, acc[0][3]);
        FMA2(acc[1][0], xa.x, w1, acc[1][0]);
        FMA2(acc[1][1], xa.y, w1, acc[1][1]);
        FMA2(acc[1][2], xb.x, w1, acc[1][2]);
        FMA2(acc[1][3], xb.y, w1, acc[1][3]);
    }

    float f[2][4];
    #pragma unroll
    for (int q = 0; q < 2; q++)
        #pragma unroll
        for (int d = 0; d < 4; d++) {
            float lo, hi; UNPACK2(lo, hi, acc[q][d]);
            f[q][d] = lo + hi;
        }
    int n0 = nt*32 + nh + 16*qh;
    if (ig == 0) { f[0][0] += b_lin[n0]; f[1][0] += b_lin[n0 + 8]; }

    float v[2][4];
    #pragma unroll
    for (int q = 0; q < 2; q++) {
        float s = f[q][0]*f[q][0] + f[q][1]*f[q][1]
                + f[q][2]*f[q][2] + f[q][3]*f[q][3];
        #pragma unroll
        for (int cc = 0; cc < 4; cc++) v[q][cc] = (c == cc) ? s : 0.f;
    }
    #pragma unroll
    for (int off = 8; off; off >>= 1) {
        #pragma unroll
        for (int q = 0; q < 2; q++)
            #pragma unroll
            for (int cc = 0; cc < 4; cc++)
                v[q][cc] += __shfl_xor_sync(0xffffffffu, v[q][cc], off);
    }
    #pragma unroll
    for (int q = 0; q < 2; q++) {
        int n = n0 + 8*q;
        float vv = (c==0)?v[q][0]:(c==1)?v[q][1]:(c==2)?v[q][2]:v[q][3];
        float gg = 1.f/(1.f + expf(-a_norm[n*4 + c]));
        float inv = 1.f/(gg*(sqrtf(vv) - 1.f) + 1.f + EPS);
        float* o = g_xr + (size_t)b*8192 + (size_t)n*64;
        o[sc2b[ig*4+0]] = f[q][0]*inv;
        o[sc2b[ig*4+1]] = f[q][1]*inv;
        o[sc2b[ig*4+2]] = f[q][2]*inv;
        o[sc2b[ig*4+3]] = f[q][3]*inv;
    }
}

// ---------------------------------------------------------------------------
// Kernel 2: out[b,n,j] = sum_k coef[n][k][j] * x[b,n,j^k] * xr[b,n,k]
// grid (n:128, jh:2, bg:4), block 256 = 8 warps.
// warp w: j-octet = jh*4 + (w&3); ko range = (w>>2)*4 .. +3.
// Warp pairs (w, w+4) each cover half the k-sum; merged via smem at the end.
// smem words: Cs2 dup pairs (j-half) [0,4096); Rp [4096,8320): k*66+2bp;
//             Xp [8320,12544): i*66+2bp.  50.2 KB -> 4 blocks/SM.
__global__ __launch_bounds__(256, 4) void k_bilinear(
    const float* __restrict__ x, const float* __restrict__ w_gp,
    const int* __restrict__ pidx, int P, float* __restrict__ out) {
    extern __shared__ float sm[];
    __shared__ int sjb[64];
    __shared__ float f4[64];
    int n = blockIdx.x, jh = blockIdx.y, bg = blockIdx.z;
    int t = threadIdx.x;
    if (t < 64) { sjb[t] = d_tab.b2s[t]; f4[t] = 0.f; }
    __syncthreads();

    // fill f4 from paths + stage x/xr (sjb ready)
    for (int p = t; p < P; p += 256) {
        int code = pidx[3*p]*16 + pidx[3*p+1]*4 + pidx[3*p+2];
        f4[code] = w_gp[n*P + p];
    }
    #pragma unroll
    for (int r = 0; r < 8; r++) {
        int p = t + 256*r;
        int i = p & 63, bq = p >> 6;
        size_t gb = (size_t)(bg*64 + 2*bq)*8192 + (size_t)n*64;
        int s = sjb[i];
        float xl = x[gb + s],      xh = x[gb + 8192 + s];
        float rl = g_xr[gb + i],   rh = g_xr[gb + 8192 + i];
        u64t pxv, prv; PACK2(pxv, xl, xh); PACK2(prv, rl, rh);
        *(u64t*)(sm + 8320 + i*66 + 2*bq) = pxv;
        *(u64t*)(sm + 4096 + i*66 + 2*bq) = prv;
    }
    __syncthreads();

    // compute coef dup-pairs for this j-half (reads f4, writes [0,4096) words)
    u64t* Cs2 = (u64t*)sm;
    #pragma unroll
    for (int r = 0; r < 8; r++) {
        int idx = t + 256*r;                 // idx = k*32 + jl
        int k = idx >> 5, jl = idx & 31;
        int j = jh*32 + jl, i = j ^ k;
        int h = (i>>1) ^ (i>>2) ^ (i>>3) ^ (i>>4) ^ (i>>5);
        float sgn = (__popc(h & k) & 1) ? -1.f : 1.f;
        int code = (__popc(i)&3)*16 + (__popc(j)&3)*4 + (__popc(k)&3);
        float c = sgn * f4[code];
        u64t pc; PACK2(pc, c, c);
        Cs2[idx] = pc;
    }
    __syncthreads();

    int lane = t & 31, w = t >> 5;
    int joL = w & 3;                 // local j-octet within half
    int jog = jh*4 + joL;            // global j-octet
    int kb = (w >> 2)*4;             // ko range start
    const u64t* pR = (const u64t*)sm + 2048 + lane;   // + k*33
    const u64t* pX = (const u64t*)sm + 4160 + lane;   // + i*33
    const ulonglong2* pC = (const ulonglong2*)sm;     // + k*16 + joL*4 + jp

    u64t acc[8];
    #pragma unroll
    for (int jj = 0; jj < 8; jj++) acc[jj] = 0ull;

    #pragma unroll
    for (int kt = 0; kt < 4; kt++) {
        int ko = kb + kt;
        int io = jog ^ ko;
        u64t xv[8];
        #pragma unroll
        for (int d = 0; d < 8; d++) xv[d] = pX[(io*8 + d)*33];
        #pragma unroll
        for (int kk = 0; kk < 8; kk++) {
            u64t rv = pR[(ko*8 + kk)*33];
            const ulonglong2* pCk = pC + (ko*8 + kk)*16 + joL*4;
            #pragma unroll
            for (int jp = 0; jp < 4; jp++) {
                ulonglong2 cc = pCk[jp];
                u64t t0, t1;
                MUL2(t0, xv[(2*jp)^kk], rv);
                FMA2(acc[2*jp], cc.x, t0, acc[2*jp]);
                MUL2(t1, xv[(2*jp+1)^kk], rv);
                FMA2(acc[2*jp+1], cc.y, t1, acc[2*jp+1]);
            }
        }
    }
    __syncthreads();
    // two partial buffers: warps 0-3 -> [0,2240), warps 4-7 -> [2240,4480)
    {
        float* Ow = sm + (w >> 2)*2240;
        #pragma unroll
        for (int jj = 0; jj < 8; jj++) {
            float lo, hi; UNPACK2(lo, hi, acc[jj]);
            int jl = joL*8 + jj;
            Ow[(2*lane)*35 + jl]   = lo;
            Ow[(2*lane+1)*35 + jl] = hi;
        }
    }
    __syncthreads();
    #pragma unroll
    for (int r = 0; r < 8; r++) {
        int idx = t + 256*r;                 // row(64) x jl(32)
        int row = idx >> 5, jl = idx & 31;
        float v = sm[row*35 + jl] + sm[2240 + row*35 + jl];
        int sj = sjb[jh*32 + jl];
        out[(size_t)(bg*64 + row)*8192 + (size_t)n*64 + sj] = v;
    }
}

// ---------------------------------------------------------------------------
extern "C" void kernel_launch(void* const* d_in, const int* in_sizes, int n_in,
                              void* d_out, int out_size) {
    const float* x      = (const float*)d_in[0];
    const float* w_gp   = (const float*)d_in[1];
    const float* w_lin  = (const float*)d_in[2];
    const float* b_lin  = (const float*)d_in[3];
    const float* a_norm = (const float*)d_in[4];
    const int*   pidx   = (const int*)d_in[7];
    int P = in_sizes[7] / 3;
    float* out = (float*)d_out;
    (void)n_in; (void)out_size;

    cudaFuncSetAttribute(k_linear,   cudaFuncAttributeMaxDynamicSharedMemorySize, 8960*4);
    cudaFuncSetAttribute(k_bilinear, cudaFuncAttributeMaxDynamicSharedMemorySize, 12544*4);

    k_wpack<<<256, 256>>>(w_lin);
    k_linear<<<1024, 256, 8960*4>>>(x, b_lin, a_norm);
    k_bilinear<<<dim3(128, 2, 4), 256, 12544*4>>>(x, w_gp, pidx, P, out);
}

// round 10
// speedup vs baseline: 1.4207x; 1.0101x over previous
#include <cuda_runtime.h>

#define EPS 1e-6f
typedef unsigned long long u64t;

#define MUL2(d,a,b)    asm("mul.rn.f32x2 %0, %1, %2;" : "=l"(d) : "l"(a), "l"(b))
#define FMA2(d,a,b,c)  asm("fma.rn.f32x2 %0, %1, %2, %3;" : "=l"(d) : "l"(a), "l"(b), "l"(c))
#define PACK2(d,lo,hi) asm("mov.b64 %0, {%1, %2};" : "=l"(d) : "f"(lo), "f"(hi))
#define UNPACK2(lo,hi,s) asm("mov.b64 {%0, %1}, %2;" : "=f"(lo), "=f"(hi) : "l"(s))

// Scratch (device globals: no allocation allowed)
__device__ float g_xr[256*128*64];     // xr in BINARY blade order, 8 MB
__device__ float g_wp[65536];          // w packed for LDG.64 streaming, 256 KB

// ---------------------------------------------------------------------------
// Compile-time blade-ordering tables (input-independent, N_GEN=6 fixed).
struct Tab { int b2s[64]; int s2c[64]; int c2b[64]; int qcls[16]; };

constexpr int popc_c(int v) { int c = 0; while (v) { c += v & 1; v >>= 1; } return c; }

constexpr Tab make_tab() {
    Tab T{};
    int s_of_b[64] = {};
    for (int b = 0; b < 64; b++) {
        int pc = popc_c(b), rank = 0;
        for (int u = 0; u < 64; u++) {
            int pu = popc_c(u);
            if (pu < pc || (pu == pc && u < b)) rank++;
        }
        s_of_b[b] = rank;
        T.b2s[b] = rank;
    }
    for (int b = 0; b < 64; b++) {
        int c = popc_c(b) & 3, s = s_of_b[b], co = 0;
        for (int u = 0; u < 64; u++) {
            int cu = popc_c(u) & 3;
            if (cu < c || (cu == c && s_of_b[u] < s)) co++;
        }
        T.s2c[s] = co;
        T.c2b[co] = b;
        if ((co & 3) == 0) T.qcls[co >> 2] = c;
    }
    return T;
}

__constant__ Tab d_tab = make_tab();

// ---------------------------------------------------------------------------
// Pack w_lin for LDG.64 streaming (gather form, coalesced STG.128):
// g_wp[nt*16384 + mp*256 + slot*8 + c*2 + par] = w_lin[(nt*32+slot)*512 + (2mp+par)*4 + c]
// Thread produces 4 consecutive outputs (c0, c0+1) x (par 0,1), c0 even.
__global__ void k_wpack(const float* __restrict__ w_lin) {
    int o4 = (blockIdx.x*128 + threadIdx.x)*4;        // 128 blocks x 128 thr
    int nt = o4 >> 14, r = o4 & 16383;
    int mp = r >> 8, r2 = r & 255;
    int slot = r2 >> 3, c0 = (r2 >> 1) & 3;           // c0 in {0,2}
    const float* src = w_lin + (nt*32 + slot)*512 + 8*mp + c0;
    float4 v;
    v.x = src[0];     // c0,   par 0
    v.y = src[4];     // c0,   par 1
    v.z = src[1];     // c0+1, par 0
    v.w = src[5];     // c0+1, par 1
    *(float4*)(g_wp + o4) = v;
}

// ---------------------------------------------------------------------------
// Kernel 1: linear mix + bias + class-norm gate, f32x2 over m-pairs.
// grid 1024 = (b:256) x (nt:4 of 32 n), block 256.
// x staged in smem (class-sorted pad-swizzle); w STREAMED from g_wp via
// LDG.64 (lanes 0-15 share a 32B sector). smem = x only -> 4 blocks/SM.
__global__ __launch_bounds__(256, 4) void k_linear(
    const float* __restrict__ x, const float* __restrict__ b_lin,
    const float* __restrict__ a_norm) {
    extern __shared__ float sm[];
    __shared__ int ss2c[64], sc2b[64], sq[16];
    int t = threadIdx.x;
    int b = blockIdx.x >> 2, nt = blockIdx.x & 3;
    if (t < 64) { ss2c[t] = d_tab.s2c[t]; sc2b[t] = d_tab.c2b[t]; }
    if (t >= 64 && t < 80) sq[t - 64] = d_tab.qcls[t - 64];
    __syncthreads();   // ss2c needed for staging

    // stage x with class-sort + pad-swizzle transpose
    {
        const float4* xg = (const float4*)(x + (size_t)b*8192);
        #pragma unroll
        for (int r = 0; r < 8; r++) {
            int idx4 = t + 256*r;
            float4 v = xg[idx4];
            int m = idx4 >> 4, s0 = (idx4 & 15)*4;
            int mp = m >> 1, par = m & 1;
            int co;
            co = ss2c[s0+0]; sm[mp*140 + co*2 + par + ((co>>4)<<2)] = v.x;
            co = ss2c[s0+1]; sm[mp*140 + co*2 + par + ((co>>4)<<2)] = v.y;
            co = ss2c[s0+2]; sm[mp*140 + co*2 + par + ((co>>4)<<2)] = v.z;
            co = ss2c[s0+3]; sm[mp*140 + co*2 + par + ((co>>4)<<2)] = v.w;
        }
    }
    __syncthreads();

    int ig = t & 15, nh = (t >> 4) & 7, qh = t >> 7;
    int c = sq[ig];
    const ulonglong2* px = (const ulonglong2*)sm + ig*2 + (ig >> 2);
    const u64t* gw = (const u64t*)g_wp + nt*8192;
    int wo0 = (nh + 16*qh)*4 + c;
    int wo1 = wo0 + 32;                 // slot + 8

    u64t acc[2][4];
    #pragma unroll
    for (int q = 0; q < 2; q++)
        #pragma unroll
        for (int d = 0; d < 4; d++) acc[q][d] = 0ull;

    #pragma unroll
    for (int mp = 0; mp < 64; mp++) {
        ulonglong2 xa = px[mp*35];
        ulonglong2 xb = px[mp*35 + 1];
        u64t w0 = gw[mp*128 + wo0];
        u64t w1 = gw[mp*128 + wo1];
        FMA2(acc[0][0], xa.x, w0, acc[0][0]);
        FMA2(acc[0][1], xa.y, w0, acc[0][1]);
        FMA2(acc[0][2], xb.x, w0, acc[0][2]);
        FMA2(acc[0][3], xb.y, w0, acc[0][3]);
        FMA2(acc[1][0], xa.x, w1, acc[1][0]);
        FMA2(acc[1][1], xa.y, w1, acc[1][1]);
        FMA2(acc[1][2], xb.x, w1, acc[1][2]);
        FMA2(acc[1][3], xb.y, w1, acc[1][3]);
    }

    float f[2][4];
    #pragma unroll
    for (int q = 0; q < 2; q++)
        #pragma unroll
        for (int d = 0; d < 4; d++) {
            float lo, hi; UNPACK2(lo, hi, acc[q][d]);
            f[q][d] = lo + hi;
        }
    int n0 = nt*32 + nh + 16*qh;
    if (ig == 0) { f[0][0] += b_lin[n0]; f[1][0] += b_lin[n0 + 8]; }

    float v[2][4];
    #pragma unroll
    for (int q = 0; q < 2; q++) {
        float s = f[q][0]*f[q][0] + f[q][1]*f[q][1]
                + f[q][2]*f[q][2] + f[q][3]*f[q][3];
        #pragma unroll
        for (int cc = 0; cc < 4; cc++) v[q][cc] = (c == cc) ? s : 0.f;
    }
    #pragma unroll
    for (int off = 8; off; off >>= 1) {
        #pragma unroll
        for (int q = 0; q < 2; q++)
            #pragma unroll
            for (int cc = 0; cc < 4; cc++)
                v[q][cc] += __shfl_xor_sync(0xffffffffu, v[q][cc], off);
    }
    #pragma unroll
    for (int q = 0; q < 2; q++) {
        int n = n0 + 8*q;
        float vv = (c==0)?v[q][0]:(c==1)?v[q][1]:(c==2)?v[q][2]:v[q][3];
        float gg = 1.f/(1.f + expf(-a_norm[n*4 + c]));
        float inv = 1.f/(gg*(sqrtf(vv) - 1.f) + 1.f + EPS);
        float* o = g_xr + (size_t)b*8192 + (size_t)n*64;
        o[sc2b[ig*4+0]] = f[q][0]*inv;
        o[sc2b[ig*4+1]] = f[q][1]*inv;
        o[sc2b[ig*4+2]] = f[q][2]*inv;
        o[sc2b[ig*4+3]] = f[q][3]*inv;
    }
}

// ---------------------------------------------------------------------------
// Kernel 2: out[b,n,j] = sum_k coef[n][k][j] * x[b,n,j^k] * xr[b,n,k]
// grid (n:128, jh:2, bg:4), block 256 = 8 warps.
// warp w: j-octet = jh*4 + (w&3); ko range = (w>>2)*4 .. +3.
// Warp pairs (w, w+4) each cover half the k-sum; merged via smem at the end.
// smem words: Cs2 dup pairs (j-half) [0,4096); Rp [4096,8320): k*66+2bp;
//             Xp [8320,12544): i*66+2bp.  50.2 KB.
__global__ __launch_bounds__(256, 4) void k_bilinear(
    const float* __restrict__ x, const float* __restrict__ w_gp,
    const int* __restrict__ pidx, int P, float* __restrict__ out) {
    extern __shared__ float sm[];
    __shared__ int sjb[64];
    __shared__ float f4[64];
    int n = blockIdx.x, jh = blockIdx.y, bg = blockIdx.z;
    int t = threadIdx.x;
    if (t < 64) { sjb[t] = d_tab.b2s[t]; f4[t] = 0.f; }
    __syncthreads();

    // fill f4 from paths + stage x/xr (sjb ready)
    for (int p = t; p < P; p += 256) {
        int code = pidx[3*p]*16 + pidx[3*p+1]*4 + pidx[3*p+2];
        f4[code] = w_gp[n*P + p];
    }
    #pragma unroll
    for (int r = 0; r < 8; r++) {
        int p = t + 256*r;
        int i = p & 63, bq = p >> 6;
        size_t gb = (size_t)(bg*64 + 2*bq)*8192 + (size_t)n*64;
        int s = sjb[i];
        float xl = x[gb + s],      xh = x[gb + 8192 + s];
        float rl = g_xr[gb + i],   rh = g_xr[gb + 8192 + i];
        u64t pxv, prv; PACK2(pxv, xl, xh); PACK2(prv, rl, rh);
        *(u64t*)(sm + 8320 + i*66 + 2*bq) = pxv;
        *(u64t*)(sm + 4096 + i*66 + 2*bq) = prv;
    }
    __syncthreads();

    // compute coef dup-pairs for this j-half (reads f4, writes [0,4096) words)
    u64t* Cs2 = (u64t*)sm;
    #pragma unroll
    for (int r = 0; r < 8; r++) {
        int idx = t + 256*r;                 // idx = k*32 + jl
        int k = idx >> 5, jl = idx & 31;
        int j = jh*32 + jl, i = j ^ k;
        int h = (i>>1) ^ (i>>2) ^ (i>>3) ^ (i>>4) ^ (i>>5);
        float sgn = (__popc(h & k) & 1) ? -1.f : 1.f;
        int code = (__popc(i)&3)*16 + (__popc(j)&3)*4 + (__popc(k)&3);
        float c = sgn * f4[code];
        u64t pc; PACK2(pc, c, c);
        Cs2[idx] = pc;
    }
    __syncthreads();

    int lane = t & 31, w = t >> 5;
    int joL = w & 3;                 // local j-octet within half
    int jog = jh*4 + joL;            // global j-octet
    int kb = (w >> 2)*4;             // ko range start
    const u64t* pR = (const u64t*)sm + 2048 + lane;   // + k*33
    const u64t* pX = (const u64t*)sm + 4160 + lane;   // + i*33
    const ulonglong2* pC = (const ulonglong2*)sm;     // + k*16 + joL*4 + jp

    u64t acc[8];
    #pragma unroll
    for (int jj = 0; jj < 8; jj++) acc[jj] = 0ull;

    #pragma unroll
    for (int kt = 0; kt < 4; kt++) {
        int ko = kb + kt;
        int io = jog ^ ko;
        u64t xv[8];
        #pragma unroll
        for (int d = 0; d < 8; d++) xv[d] = pX[(io*8 + d)*33];
        #pragma unroll
        for (int kk = 0; kk < 8; kk++) {
            u64t rv = pR[(ko*8 + kk)*33];
            const ulonglong2* pCk = pC + (ko*8 + kk)*16 + joL*4;
            #pragma unroll
            for (int jp = 0; jp < 4; jp++) {
                ulonglong2 cc = pCk[jp];
                u64t t0, t1;
                MUL2(t0, xv[(2*jp)^kk], rv);
                FMA2(acc[2*jp], cc.x, t0, acc[2*jp]);
                MUL2(t1, xv[(2*jp+1)^kk], rv);
                FMA2(acc[2*jp+1], cc.y, t1, acc[2*jp+1]);
            }
        }
    }
    __syncthreads();
    // two partial buffers: warps 0-3 -> [0,2240), warps 4-7 -> [2240,4480)
    {
        float* Ow = sm + (w >> 2)*2240;
        #pragma unroll
        for (int jj = 0; jj < 8; jj++) {
            float lo, hi; UNPACK2(lo, hi, acc[jj]);
            int jl = joL*8 + jj;
            Ow[(2*lane)*35 + jl]   = lo;
            Ow[(2*lane+1)*35 + jl] = hi;
        }
    }
    __syncthreads();
    #pragma unroll
    for (int r = 0; r < 8; r++) {
        int idx = t + 256*r;                 // row(64) x jl(32)
        int row = idx >> 5, jl = idx & 31;
        float v = sm[row*35 + jl] + sm[2240 + row*35 + jl];
        int sj = sjb[jh*32 + jl];
        out[(size_t)(bg*64 + row)*8192 + (size_t)n*64 + sj] = v;
    }
}

// ---------------------------------------------------------------------------
extern "C" void kernel_launch(void* const* d_in, const int* in_sizes, int n_in,
                              void* d_out, int out_size) {
    const float* x      = (const float*)d_in[0];
    const float* w_gp   = (const float*)d_in[1];
    const float* w_lin  = (const float*)d_in[2];
    const float* b_lin  = (const float*)d_in[3];
    const float* a_norm = (const float*)d_in[4];
    const int*   pidx   = (const int*)d_in[7];
    int P = in_sizes[7] / 3;
    float* out = (float*)d_out;
    (void)n_in; (void)out_size;

    cudaFuncSetAttribute(k_linear,   cudaFuncAttributeMaxDynamicSharedMemorySize, 8960*4);
    cudaFuncSetAttribute(k_bilinear, cudaFuncAttributeMaxDynamicSharedMemorySize, 12544*4);

    k_wpack<<<128, 128>>>(w_lin);
    k_linear<<<1024, 256, 8960*4>>>(x, b_lin, a_norm);
    k_bilinear<<<dim3(128, 2, 4), 256, 12544*4>>>(x, w_gp, pidx, P, out);
}